// round 2
// baseline (speedup 1.0000x reference)
#include <cuda_runtime.h>

#define BSZ 512
#define NN 1000
#define D 128
#define STR 384   // K_att/V_att innermost stride in floats (3 layers * 128)

// One CTA per batch. 256 threads = 8 warps.
// Warp w processes compacted-node-list positions w, w+8, w+16, ...
// Lanes split a 128-float row into float4 chunks: lane t owns floats [4t, 4t+4).
// For 8-head (dh=16) attention, head h = lane>>2; 4-lane shfl_xor reduces the dot.

__global__ __launch_bounds__(256, 4)
void decoder_fused_kernel(
    const float* __restrict__ query,
    const float* __restrict__ K_att,
    const float* __restrict__ V_att,
    const int* __restrict__ mask,          // bool serialized as int32
    const float* __restrict__ W0_w,
    const float* __restrict__ W0_b,
    const float* __restrict__ Wq_w,
    const float* __restrict__ Wq_b,
    float* __restrict__ out)
{
    __shared__ int nlist[NN];
    __shared__ int cnt_s;
    __shared__ __align__(16) float qs[D];   // current query
    __shared__ __align__(16) float mo[D];   // mha output / q_final
    __shared__ float m_s[8][32];
    __shared__ float l_s[8][32];
    __shared__ __align__(16) float4 a_s[8][32];
    __shared__ float M2s, L2s;

    const int b = blockIdx.x;
    const int tid = threadIdx.x;
    const int wid = tid >> 5;
    const int lane = tid & 31;

    if (tid < D) qs[tid] = query[(size_t)b * D + tid];

    // ---- Compact unmasked node list (deterministic order, warp 0) ----
    const int* mrow = mask + (size_t)b * NN;
    if (wid == 0) {
        int base = 0;
        for (int start = 0; start < NN; start += 32) {
            int n = start + lane;
            bool keep = (n < NN) && (mrow[n] == 0);
            unsigned bal = __ballot_sync(0xffffffffu, keep);
            if (keep) {
                int pos = base + __popc(bal & ((1u << lane) - 1u));
                nlist[pos] = n;
            }
            base += __popc(bal);
        }
        if (lane == 0) cnt_s = base;
    }
    __syncthreads();
    const int cnt = cnt_s;

    const float* Kb = K_att + (size_t)b * NN * STR;
    const float* Vb = V_att + (size_t)b * NN * STR;

    // ==================== Layers 0 and 1: 8-head MHA + W0 linear ====================
    for (int l = 0; l < 2; ++l) {
        const int coff = l * D + 4 * lane;
        const float4 q4 = *(const float4*)(qs + 4 * lane);

        float m = -1e30f, lsum = 0.0f;
        float4 acc = make_float4(0.f, 0.f, 0.f, 0.f);

        int p = wid;
        float4 k4 = make_float4(0.f, 0.f, 0.f, 0.f);
        float4 v4 = make_float4(0.f, 0.f, 0.f, 0.f);
        if (p < cnt) {
            size_t off = (size_t)nlist[p] * STR + coff;
            k4 = *(const float4*)(Kb + off);
            v4 = *(const float4*)(Vb + off);
        }
        while (p < cnt) {
            const float4 kc = k4;
            const float4 vc = v4;
            const int pn = p + 8;
            if (pn < cnt) {  // prefetch next node (keeps ~4 lines/warp in flight)
                size_t off = (size_t)nlist[pn] * STR + coff;
                k4 = *(const float4*)(Kb + off);
                v4 = *(const float4*)(Vb + off);
            }
            // per-head dot: reduce over the 4 lanes of this head
            float s = kc.x * q4.x + kc.y * q4.y + kc.z * q4.z + kc.w * q4.w;
            s += __shfl_xor_sync(0xffffffffu, s, 1);
            s += __shfl_xor_sync(0xffffffffu, s, 2);
            s *= 0.25f;  // 1/sqrt(16)

            const float mnew = fmaxf(m, s);
            const float corr = __expf(m - mnew);
            const float pexp = __expf(s - mnew);
            lsum = lsum * corr + pexp;
            acc.x = acc.x * corr + pexp * vc.x;
            acc.y = acc.y * corr + pexp * vc.y;
            acc.z = acc.z * corr + pexp * vc.z;
            acc.w = acc.w * corr + pexp * vc.w;
            m = mnew;
            p = pn;
        }

        m_s[wid][lane] = m;
        l_s[wid][lane] = lsum;
        a_s[wid][lane] = acc;
        __syncthreads();

        // merge the 8 warp-partials (lane t of warp 0 merges slot t)
        if (tid < 32) {
            float M = m_s[0][lane];
            #pragma unroll
            for (int w = 1; w < 8; ++w) M = fmaxf(M, m_s[w][lane]);
            float L = 0.f;
            float ax = 0.f, ay = 0.f, az = 0.f, aw = 0.f;
            #pragma unroll
            for (int w = 0; w < 8; ++w) {
                const float c = __expf(m_s[w][lane] - M);
                L += l_s[w][lane] * c;
                const float4 a = a_s[w][lane];
                ax += a.x * c; ay += a.y * c; az += a.z * c; aw += a.w * c;
            }
            const float inv = 1.0f / L;
            mo[4 * lane + 0] = ax * inv;
            mo[4 * lane + 1] = ay * inv;
            mo[4 * lane + 2] = az * inv;
            mo[4 * lane + 3] = aw * inv;
        }
        __syncthreads();

        // query = mha_out @ W0_w.T + W0_b
        if (tid < D) {
            const float* Wr = W0_w + tid * D;
            float a2 = W0_b[tid];
            #pragma unroll 8
            for (int d = 0; d < D; ++d) a2 = fmaf(mo[d], Wr[d], a2);
            qs[tid] = a2;
        }
        __syncthreads();
    }

    // ==================== Layer 2: q_final = q @ Wq.T + b; 1-head, clip=10 ====================
    if (tid < D) {
        const float* Wr = Wq_w + tid * D;
        float a2 = Wq_b[tid];
        #pragma unroll 8
        for (int d = 0; d < D; ++d) a2 = fmaf(qs[d], Wr[d], a2);
        mo[tid] = a2;
    }
    __syncthreads();

    {
        const float4 q4 = *(const float4*)(mo + 4 * lane);
        const int coff = 2 * D + 4 * lane;
        float* orow = out + (size_t)b * NN;

        float m = -1e30f, lsum = 0.0f;
        int p = wid;
        float4 k4 = make_float4(0.f, 0.f, 0.f, 0.f);
        int ncur = 0;
        if (p < cnt) {
            ncur = nlist[p];
            k4 = *(const float4*)(Kb + (size_t)ncur * STR + coff);
        }
        while (p < cnt) {
            const float4 kc = k4;
            const int n = ncur;
            const int pn = p + 8;
            if (pn < cnt) {
                ncur = nlist[pn];
                k4 = *(const float4*)(Kb + (size_t)ncur * STR + coff);
            }
            float s = kc.x * q4.x + kc.y * q4.y + kc.z * q4.z + kc.w * q4.w;
            s += __shfl_xor_sync(0xffffffffu, s, 1);
            s += __shfl_xor_sync(0xffffffffu, s, 2);
            s += __shfl_xor_sync(0xffffffffu, s, 4);
            s += __shfl_xor_sync(0xffffffffu, s, 8);
            s += __shfl_xor_sync(0xffffffffu, s, 16);
            s *= 0.08838834764831845f;  // 1/sqrt(128)
            s = 10.0f * tanhf(s);       // clip

            const float mnew = fmaxf(m, s);
            lsum = lsum * __expf(m - mnew) + __expf(s - mnew);
            m = mnew;
            if (lane == 0) orow[n] = s;  // stage unnormalized logit
            p = pn;
        }
        if (lane == 0) { m_s[wid][0] = m; l_s[wid][0] = lsum; }
        __syncthreads();
        if (tid == 0) {
            float M = m_s[0][0];
            #pragma unroll
            for (int w = 1; w < 8; ++w) M = fmaxf(M, m_s[w][0]);
            float L = 0.f;
            #pragma unroll
            for (int w = 0; w < 8; ++w) L += l_s[w][0] * __expf(m_s[w][0] - M);
            M2s = M;
            L2s = 1.0f / L;
        }
        __syncthreads();

        const float M = M2s, Li = L2s;
        for (int n = tid; n < NN; n += 256) {
            float v = 0.0f;
            if (mrow[n] == 0) v = __expf(orow[n] - M) * Li;
            orow[n] = v;
        }
    }
}

extern "C" void kernel_launch(void* const* d_in, const int* in_sizes, int n_in,
                              void* d_out, int out_size) {
    const float* query = (const float*)d_in[0];
    const float* K_att = (const float*)d_in[1];
    const float* V_att = (const float*)d_in[2];
    const int*   mask  = (const int*)d_in[3];
    const float* W0_w  = (const float*)d_in[4];
    const float* W0_b  = (const float*)d_in[5];
    const float* Wq_w  = (const float*)d_in[6];
    const float* Wq_b  = (const float*)d_in[7];
    float* out = (float*)d_out;

    decoder_fused_kernel<<<BSZ, 256>>>(query, K_att, V_att, mask,
                                       W0_w, W0_b, Wq_w, Wq_b, out);
}